// round 2
// baseline (speedup 1.0000x reference)
#include <cuda_runtime.h>
#include <cstdint>

// ConvDemodulated: out[b,o,hw] = clip( sum_i x[b,i,hw] * Wn[o,i] + bias[o], -256, 256 )
// Wn = row-normalized weight. Implemented as tf32 mma.sync GEMM:
//   D[cout=64][pix] = Wn[64][64] * X[64][pix], fp32 accumulate.
// tcgen05 is unavailable (harness compiles via compute_103, no 'a' features),
// so we use the baseline mma.sync tensor path.

#define CIN   64
#define COUT  64
#define HWSZ  65536      // 256*256
#define PTILE 128        // pixels per CTA
#define PAD   136        // smem row stride in floats: 8*tig bank offset -> conflict-free B-frag LDS

// Pre-shuffled weight fragments: [cw(4)][lane(32)][ks(8)][j(4)] tf32 bit patterns.
__device__ float g_wfrag[4 * 32 * 8 * 4];

__device__ __forceinline__ uint32_t f2tf32(float f) {
    uint32_t u;
    asm("cvt.rna.tf32.f32 %0, %1;" : "=r"(u) : "f"(f));
    return u;
}

// ---------------- weight prep: normalize rows, tf32-round, shuffle to fragment order --------
__global__ void prep_w_kernel(const float* __restrict__ w) {
    __shared__ float wn[COUT * CIN];
    const int t = threadIdx.x;  // 64 threads, one cout row each
    float s = 1e-8f;
#pragma unroll
    for (int k = 0; k < CIN; k++) {
        float v = w[t * CIN + k];
        s += v * v;
    }
    const float d = rsqrtf(s);
#pragma unroll
    for (int k = 0; k < CIN; k++)
        wn[t * CIN + k] = __uint_as_float(f2tf32(w[t * CIN + k] * d));
    __syncthreads();

    // Fragment order for mma.m16n8k8.tf32 A-operand (row-major):
    // a0=(r,c) a1=(r+8,c) a2=(r,c+4) a3=(r+8,c+4); r = 16*cw + (lane>>2), c = 8*ks + (lane&3)
    for (int e = t; e < 4096; e += 64) {
        int cw = e >> 10, lane = (e >> 5) & 31, ks = (e >> 2) & 7, j = e & 3;
        int r = cw * 16 + (lane >> 2) + 8 * (j & 1);
        int c = ks * 8 + (lane & 3) + 4 * (j >> 1);
        g_wfrag[e] = wn[r * CIN + c];
    }
}

// ---------------- main kernel ----------------
__global__ void __launch_bounds__(256, 2)
conv_mma_kernel(const float* __restrict__ x, const float* __restrict__ bias,
                float* __restrict__ out) {
    __shared__ float sx[CIN][PAD];   // x tile, tf32-rounded bit patterns

    const int tid  = threadIdx.x;
    const int lane = tid & 31;
    const int wid  = tid >> 5;
    const int cw   = wid & 3;        // cout group: rows [16*cw, 16*cw+16)
    const int ph   = wid >> 2;       // pixel half: cols [64*ph, 64*ph+64)

    const int pixglob = blockIdx.x * PTILE;        // never straddles a batch image
    const int b   = pixglob >> 16;
    const int hw0 = pixglob & (HWSZ - 1);
    const float* xb = x + ((size_t)b << 22) + hw0; // + b*64*65536

    // ---- stage X tile (64 x 128 fp32) into smem, rounding to tf32 ----
    // Each warp loads one full k-row per iteration as float4 (coalesced 512B).
#pragma unroll
    for (int it = 0; it < 8; it++) {
        int idx = it * 256 + tid;       // 0..2047 float4 slots
        int k   = idx >> 5;             // k-row (constant per warp)
        int p4  = idx & 31;             // float4 index within row
        float4 v = *(const float4*)(xb + ((size_t)k << 16) + (size_t)p4 * 4);
        v.x = __uint_as_float(f2tf32(v.x));
        v.y = __uint_as_float(f2tf32(v.y));
        v.z = __uint_as_float(f2tf32(v.z));
        v.w = __uint_as_float(f2tf32(v.w));
        *(float4*)&sx[k][p4 * 4] = v;
    }

    // ---- load A fragments (weights) from pre-shuffled gmem (L1-hot, 8x LDG.128) ----
    uint32_t a[8][4];
    {
        const float4* wf = (const float4*)(g_wfrag + ((cw * 32 + lane) << 5));
#pragma unroll
        for (int ks = 0; ks < 8; ks++) {
            float4 v = __ldg(wf + ks);
            a[ks][0] = __float_as_uint(v.x);
            a[ks][1] = __float_as_uint(v.y);
            a[ks][2] = __float_as_uint(v.z);
            a[ks][3] = __float_as_uint(v.w);
        }
    }

    float acc[8][4];
#pragma unroll
    for (int nt = 0; nt < 8; nt++)
#pragma unroll
        for (int j = 0; j < 4; j++) acc[nt][j] = 0.0f;

    __syncthreads();

    // ---- main loop: 8 k-steps x 8 n-tiles of m16n8k8 ----
    const int tig  = lane & 3;   // thread-in-group (k index within frag)
    const int gid  = lane >> 2;  // group id (pixel index within 8-col tile)
    const int pixb = ph * 64;

#pragma unroll
    for (int ks = 0; ks < 8; ks++) {
#pragma unroll
        for (int nt = 0; nt < 8; nt++) {
            // B fragment (col-major 8x8): b0 = X[k=8ks+tig][pix], b1 = X[k+4][pix]
            uint32_t b0 = __float_as_uint(sx[ks * 8 + tig    ][pixb + nt * 8 + gid]);
            uint32_t b1 = __float_as_uint(sx[ks * 8 + tig + 4][pixb + nt * 8 + gid]);
            asm volatile(
                "mma.sync.aligned.m16n8k8.row.col.f32.tf32.tf32.f32 "
                "{%0,%1,%2,%3}, {%4,%5,%6,%7}, {%8,%9}, {%0,%1,%2,%3};"
                : "+f"(acc[nt][0]), "+f"(acc[nt][1]), "+f"(acc[nt][2]), "+f"(acc[nt][3])
                : "r"(a[ks][0]), "r"(a[ks][1]), "r"(a[ks][2]), "r"(a[ks][3]),
                  "r"(b0), "r"(b1));
        }
    }

    // ---- epilogue: bias + clamp, float2 stores (sector-optimal) ----
    const int row0 = cw * 16 + gid;
    const float bv0 = __ldg(bias + row0);
    const float bv1 = __ldg(bias + row0 + 8);
    float* ob = out + ((size_t)b << 22) + hw0;

#pragma unroll
    for (int nt = 0; nt < 8; nt++) {
        int col = pixb + nt * 8 + tig * 2;
        float2 v0, v1;
        v0.x = fminf(fmaxf(acc[nt][0] + bv0, -256.0f), 256.0f);
        v0.y = fminf(fmaxf(acc[nt][1] + bv0, -256.0f), 256.0f);
        v1.x = fminf(fmaxf(acc[nt][2] + bv1, -256.0f), 256.0f);
        v1.y = fminf(fmaxf(acc[nt][3] + bv1, -256.0f), 256.0f);
        *(float2*)(ob + ((size_t)row0       << 16) + col) = v0;
        *(float2*)(ob + ((size_t)(row0 + 8) << 16) + col) = v1;
    }
}

// ---------------- launch ----------------
extern "C" void kernel_launch(void* const* d_in, const int* in_sizes, int n_in,
                              void* d_out, int out_size) {
    const float* x    = (const float*)d_in[0];
    const float* w    = (const float*)d_in[1];
    const float* bias = (const float*)d_in[2];
    float* out = (float*)d_out;

    prep_w_kernel<<<1, COUT>>>(w);

    const int total_pix = 16 * HWSZ;           // B*H*W = 1,048,576
    const int nblocks = total_pix / PTILE;     // 8192
    conv_mma_kernel<<<nblocks, 256>>>(x, bias, out);
}

// round 3
// speedup vs baseline: 1.3345x; 1.3345x over previous
#include <cuda_runtime.h>
#include <cstdint>

// ConvDemodulated: out[b,o,hw] = clip( sum_i x[b,i,hw] * Wn[o,i] + bias[o], -256, 256 )
// tf32 mma.sync GEMM: D[64 cout][pix] = Wn[64][64] * X[64][pix], fp32 accumulate.
// R3: pair-packed smem (LDS.64 B-frags), 32cout x 64pix warp tiles (halved LDS
// redundancy), STS.128 staging, per-ks W A-frags from L1-hot pre-shuffled gmem.

#define CIN   64
#define COUT  64
#define HWSZ  65536
#define PTILE 128        // pixels per CTA
#define S2    136        // smem row stride in float2 (mod 16 == 8 -> conflict-free LDS.64)

// Pre-shuffled weight A-fragments: [ks(8)][mt(4)][lane(32)][j(4)] tf32 bits.
__device__ float g_wfrag[8 * 4 * 32 * 4];

__device__ __forceinline__ uint32_t f2tf32(float f) {
    uint32_t u;
    asm("cvt.rna.tf32.f32 %0, %1;" : "=r"(u) : "f"(f));
    return u;
}

// ---------------- weight prep ----------------
__global__ void prep_w_kernel(const float* __restrict__ w) {
    __shared__ float wn[COUT * CIN];
    const int t = threadIdx.x;  // 64 threads
    float s = 1e-8f;
#pragma unroll
    for (int k = 0; k < CIN; k++) {
        float v = w[t * CIN + k];
        s += v * v;
    }
    const float d = rsqrtf(s);
#pragma unroll
    for (int k = 0; k < CIN; k++)
        wn[t * CIN + k] = __uint_as_float(f2tf32(w[t * CIN + k] * d));
    __syncthreads();

    // A-frag order (m16n8k8 row-major): j=0:(g,t) 1:(g+8,t) 2:(g,t+4) 3:(g+8,t+4)
    for (int e = t; e < 4096; e += 64) {
        int j = e & 3, lane = (e >> 2) & 31, mt = (e >> 7) & 3, ks = e >> 9;
        int r = mt * 16 + (lane >> 2) + 8 * (j & 1);
        int c = ks * 8 + (lane & 3) + 4 * (j >> 1);
        g_wfrag[e] = wn[r * CIN + c];
    }
}

// ---------------- main kernel ----------------
__global__ void __launch_bounds__(128, 4)
conv_mma_kernel(const float* __restrict__ x, const float* __restrict__ bias,
                float* __restrict__ out) {
    // spair[kp][pix] = float2( X[8*(kp>>2)+(kp&3)][pix], X[...+4][pix] ), tf32 bits
    __shared__ __align__(16) float2 spair[32][S2];

    const int tid  = threadIdx.x;
    const int lane = tid & 31;
    const int wid  = tid >> 5;        // 0..3
    const int cw   = wid & 1;         // cout half: rows [32*cw, 32*cw+32)
    const int ph   = wid >> 1;        // pixel half: cols [64*ph, 64*ph+64)

    const int pixglob = blockIdx.x * PTILE;
    const int b   = pixglob >> 16;
    const int hw0 = pixglob & (HWSZ - 1);
    const float* xb = x + ((size_t)b << 22) + hw0;

    // ---- stage X tile: 32 row-pairs x 128 pixels, tf32-rounded, pair-packed ----
#pragma unroll
    for (int it = 0; it < 8; it++) {
        const int rp = it * 4 + wid;            // 0..31 == kp
        const int k  = (rp >> 2) * 8 + (rp & 3);
        const int p0 = lane * 4;
        float4 v0 = *(const float4*)(xb + ((size_t)k << 16) + p0);
        float4 v1 = *(const float4*)(xb + ((size_t)(k + 4) << 16) + p0);
        float4 w0, w1;
        w0.x = __uint_as_float(f2tf32(v0.x)); w0.y = __uint_as_float(f2tf32(v1.x));
        w0.z = __uint_as_float(f2tf32(v0.y)); w0.w = __uint_as_float(f2tf32(v1.y));
        w1.x = __uint_as_float(f2tf32(v0.z)); w1.y = __uint_as_float(f2tf32(v1.z));
        w1.z = __uint_as_float(f2tf32(v0.w)); w1.w = __uint_as_float(f2tf32(v1.w));
        *(float4*)&spair[rp][p0]     = w0;   // pixels p0, p0+1
        *(float4*)&spair[rp][p0 + 2] = w1;   // pixels p0+2, p0+3
    }
    __syncthreads();

    // ---- mma mainloop: 8 ks x 8 nt x 2 m-tiles ----
    const int t    = lane & 3;
    const int g    = lane >> 2;
    const int pixb = ph * 64;

    float acc[2][8][4];
#pragma unroll
    for (int m = 0; m < 2; m++)
#pragma unroll
        for (int nt = 0; nt < 8; nt++)
#pragma unroll
            for (int j = 0; j < 4; j++) acc[m][nt][j] = 0.0f;

#pragma unroll
    for (int ks = 0; ks < 8; ks++) {
        // W A-frags for this ks (L1-hot: 16KB working set shared by all CTAs)
        uint32_t a[2][4];
#pragma unroll
        for (int m = 0; m < 2; m++) {
            const float4 wv = __ldg((const float4*)g_wfrag +
                                    ((ks * 4 + cw * 2 + m) * 32 + lane));
            a[m][0] = __float_as_uint(wv.x);
            a[m][1] = __float_as_uint(wv.y);
            a[m][2] = __float_as_uint(wv.z);
            a[m][3] = __float_as_uint(wv.w);
        }
#pragma unroll
        for (int nt = 0; nt < 8; nt++) {
            const float2 bb = spair[ks * 4 + t][pixb + nt * 8 + g];
            const uint32_t b0 = __float_as_uint(bb.x);
            const uint32_t b1 = __float_as_uint(bb.y);
#pragma unroll
            for (int m = 0; m < 2; m++) {
                asm volatile(
                    "mma.sync.aligned.m16n8k8.row.col.f32.tf32.tf32.f32 "
                    "{%0,%1,%2,%3}, {%4,%5,%6,%7}, {%8,%9}, {%0,%1,%2,%3};"
                    : "+f"(acc[m][nt][0]), "+f"(acc[m][nt][1]),
                      "+f"(acc[m][nt][2]), "+f"(acc[m][nt][3])
                    : "r"(a[m][0]), "r"(a[m][1]), "r"(a[m][2]), "r"(a[m][3]),
                      "r"(b0), "r"(b1));
            }
        }
    }

    // ---- epilogue: bias + clamp, float2 stores ----
    float* ob = out + ((size_t)b << 22) + hw0;
#pragma unroll
    for (int m = 0; m < 2; m++) {
        const int row0 = cw * 32 + m * 16 + g;
        const float bv0 = __ldg(bias + row0);
        const float bv1 = __ldg(bias + row0 + 8);
#pragma unroll
        for (int nt = 0; nt < 8; nt++) {
            const int col = pixb + nt * 8 + t * 2;
            float2 v0, v1;
            v0.x = fminf(fmaxf(acc[m][nt][0] + bv0, -256.0f), 256.0f);
            v0.y = fminf(fmaxf(acc[m][nt][1] + bv0, -256.0f), 256.0f);
            v1.x = fminf(fmaxf(acc[m][nt][2] + bv1, -256.0f), 256.0f);
            v1.y = fminf(fmaxf(acc[m][nt][3] + bv1, -256.0f), 256.0f);
            *(float2*)(ob + ((size_t)row0       << 16) + col) = v0;
            *(float2*)(ob + ((size_t)(row0 + 8) << 16) + col) = v1;
        }
    }
}

// ---------------- launch ----------------
extern "C" void kernel_launch(void* const* d_in, const int* in_sizes, int n_in,
                              void* d_out, int out_size) {
    const float* x    = (const float*)d_in[0];
    const float* w    = (const float*)d_in[1];
    const float* bias = (const float*)d_in[2];
    float* out = (float*)d_out;

    prep_w_kernel<<<1, COUT>>>(w);

    const int total_pix = 16 * HWSZ;
    const int nblocks = total_pix / PTILE;   // 8192
    conv_mma_kernel<<<nblocks, 128>>>(x, bias, out);
}

// round 5
// speedup vs baseline: 1.6908x; 1.2670x over previous
#include <cuda_runtime.h>
#include <cuda_fp16.h>
#include <cstdint>

// ConvDemodulated: out[b,o,hw] = clip( sum_i x[b,i,hw] * Wn[o,i] + bias[o], -256, 256 )
// R4: fp16 mma.m16n8k16 (same 10-bit mantissa as tf32, half the bytes),
// pair-packed uint2 B-frags (1 LDS.64 per frag), coalesced smem-transpose epilogue.

#define CIN   64
#define COUT  64
#define HWSZ  65536
#define PTILE 128      // pixels per CTA
#define S2U   132      // staging stride (uint2 units), mod 16 == 4 -> conflict-free LDS.64
#define SEF   136      // epilogue stride (floats), float2-pair mapping even 2-to-1

// Pre-packed fp16 A-fragments: [kb(4)][mt(4)][lane(32)] uint4 (8 halves each).
__device__ uint4 g_wfrag16[4 * 4 * 32];

__device__ __forceinline__ uint32_t pack_h2(float lo, float hi) {
    __half2 h = __floats2half2_rn(lo, hi);
    return *reinterpret_cast<uint32_t*>(&h);
}

// ---------------- weight prep: normalize rows, pack m16n8k16 A-frags ----------------
__global__ void prep_w_kernel(const float* __restrict__ w) {
    __shared__ float wn[COUT * CIN];
    const int t = threadIdx.x;  // 64 threads
    float s = 1e-8f;
#pragma unroll
    for (int k = 0; k < CIN; k++) {
        float v = w[t * CIN + k];
        s += v * v;
    }
    const float d = rsqrtf(s);
#pragma unroll
    for (int k = 0; k < CIN; k++)
        wn[t * CIN + k] = w[t * CIN + k] * d;
    __syncthreads();

    // A-frag (m16n8k16 row-major): a0=(r,c|c+1) a1=(r+8,c|c+1) a2=(r,c+8|c+9) a3=(r+8,c+8|c+9)
    // r = mt*16 + lane/4, c = kb*16 + 2*(lane%4)
    for (int e = t; e < 512; e += 64) {
        int lane = e & 31, mt = (e >> 5) & 3, kb = e >> 7;
        int r = mt * 16 + (lane >> 2);
        int c = kb * 16 + 2 * (lane & 3);
        uint4 v;
        v.x = pack_h2(wn[r * CIN + c],           wn[r * CIN + c + 1]);
        v.y = pack_h2(wn[(r + 8) * CIN + c],     wn[(r + 8) * CIN + c + 1]);
        v.z = pack_h2(wn[r * CIN + c + 8],       wn[r * CIN + c + 9]);
        v.w = pack_h2(wn[(r + 8) * CIN + c + 8], wn[(r + 8) * CIN + c + 9]);
        g_wfrag16[(kb * 4 + mt) * 32 + lane] = v;
    }
}

// ---------------- main kernel ----------------
__global__ void __launch_bounds__(128, 4)
conv_mma_kernel(const float* __restrict__ x, const float* __restrict__ bias,
                float* __restrict__ out) {
    // Union: staging (16 quad-rows x 132 uint2 = 16.9KB) then epilogue (64 x 136 fp32 = 34.8KB)
    __shared__ __align__(16) float SE[COUT * SEF];
    uint2* SB = (uint2*)SE;

    const int tid  = threadIdx.x;
    const int lane = tid & 31;
    const int wid  = tid >> 5;     // 0..3
    const int cw   = wid & 1;      // cout half
    const int ph   = wid >> 1;     // pixel half

    const int pixglob = blockIdx.x * PTILE;
    const int b   = pixglob >> 16;
    const int hw0 = pixglob & (HWSZ - 1);
    const float* xb = x + ((size_t)b << 22) + hw0;

    // ---- stage X: quad-row q holds halves of k rows {k0,k0+1} (lo/hi of .x) and {k0+8,k0+9} (.y) ----
#pragma unroll
    for (int it = 0; it < 4; it++) {
        const int q  = it * 4 + wid;                 // 0..15
        const int k0 = ((q >> 2) << 4) + ((q & 3) << 1);
        const float* rp = xb + ((size_t)k0 << 16) + lane * 4;
        float4 va = *(const float4*)(rp);
        float4 vb = *(const float4*)(rp + (1 << 16));
        float4 vc = *(const float4*)(rp + (8 << 16));
        float4 vd = *(const float4*)(rp + (9 << 16));
        uint4 o0, o1;
        o0.x = pack_h2(va.x, vb.x); o0.y = pack_h2(vc.x, vd.x);
        o0.z = pack_h2(va.y, vb.y); o0.w = pack_h2(vc.y, vd.y);
        o1.x = pack_h2(va.z, vb.z); o1.y = pack_h2(vc.z, vd.z);
        o1.z = pack_h2(va.w, vb.w); o1.w = pack_h2(vc.w, vd.w);
        *(uint4*)&SB[q * S2U + lane * 4]     = o0;
        *(uint4*)&SB[q * S2U + lane * 4 + 2] = o1;
    }

    // ---- A-fragments (all 4 k-blocks x 2 m-tiles), L1-hot pre-packed ----
    uint4 aw[2][4];
#pragma unroll
    for (int m = 0; m < 2; m++)
#pragma unroll
        for (int kb = 0; kb < 4; kb++)
            aw[m][kb] = __ldg(&g_wfrag16[(kb * 4 + cw * 2 + m) * 32 + lane]);

    float acc[2][8][4];
#pragma unroll
    for (int m = 0; m < 2; m++)
#pragma unroll
        for (int nt = 0; nt < 8; nt++)
#pragma unroll
            for (int j = 0; j < 4; j++) acc[m][nt][j] = 0.0f;

    __syncthreads();

    // ---- mainloop: 4 k-blocks x 8 n-tiles x 2 m-tiles of m16n8k16 ----
    const int t    = lane & 3;
    const int g    = lane >> 2;
    const int pixb = ph * 64;

#pragma unroll
    for (int kb = 0; kb < 4; kb++) {
#pragma unroll
        for (int nt = 0; nt < 8; nt++) {
            const uint2 bb = SB[(kb * 4 + t) * S2U + pixb + nt * 8 + g];
#pragma unroll
            for (int m = 0; m < 2; m++) {
                asm volatile(
                    "mma.sync.aligned.m16n8k16.row.col.f32.f16.f16.f32 "
                    "{%0,%1,%2,%3}, {%4,%5,%6,%7}, {%8,%9}, {%0,%1,%2,%3};"
                    : "+f"(acc[m][nt][0]), "+f"(acc[m][nt][1]),
                      "+f"(acc[m][nt][2]), "+f"(acc[m][nt][3])
                    : "r"(aw[m][kb].x), "r"(aw[m][kb].y),
                      "r"(aw[m][kb].z), "r"(aw[m][kb].w),
                      "r"(bb.x), "r"(bb.y));
            }
        }
    }

    __syncthreads();   // mainloop smem reads done before union overwrite

    // ---- epilogue pt1: bias+clamp in regs, STS into [cout][pix] (even 2-to-1 bank pairs) ----
#pragma unroll
    for (int m = 0; m < 2; m++) {
        const int row0 = cw * 32 + m * 16 + g;
        const float bv0 = __ldg(bias + row0);
        const float bv1 = __ldg(bias + row0 + 8);
#pragma unroll
        for (int nt = 0; nt < 8; nt++) {
            const int col = pixb + nt * 8 + t * 2;
            float2 v0, v1;
            v0.x = fminf(fmaxf(acc[m][nt][0] + bv0, -256.0f), 256.0f);
            v0.y = fminf(fmaxf(acc[m][nt][1] + bv0, -256.0f), 256.0f);
            v1.x = fminf(fmaxf(acc[m][nt][2] + bv1, -256.0f), 256.0f);
            v1.y = fminf(fmaxf(acc[m][nt][3] + bv1, -256.0f), 256.0f);
            *(float2*)&SE[row0 * SEF + col]       = v0;
            *(float2*)&SE[(row0 + 8) * SEF + col] = v1;
        }
    }
    __syncthreads();

    // ---- epilogue pt2: coalesced 512B-per-warp copy out ----
    float* ob = out + ((size_t)b << 22) + hw0;
#pragma unroll
    for (int p = 0; p < 16; p++) {
        const int row = p * 4 + wid;               // cout
        float4 v = *(const float4*)&SE[row * SEF + lane * 4];
        *(float4*)(ob + ((size_t)row << 16) + lane * 4) = v;
    }
}

// ---------------- launch ----------------
extern "C" void kernel_launch(void* const* d_in, const int* in_sizes, int n_in,
                              void* d_out, int out_size) {
    const float* x    = (const float*)d_in[0];
    const float* w    = (const float*)d_in[1];
    const float* bias = (const float*)d_in[2];
    float* out = (float*)d_out;

    prep_w_kernel<<<1, COUT>>>(w);

    const int total_pix = 16 * HWSZ;
    const int nblocks = total_pix / PTILE;   // 8192
    conv_mma_kernel<<<nblocks, 128>>>(x, bias, out);
}